// round 1
// baseline (speedup 1.0000x reference)
#include <cuda_runtime.h>
#include <cstdint>

// ---------------------------------------------------------------------------
// Problem constants
// ---------------------------------------------------------------------------
#define N_ROWS 16384      // 64 * 256
#define N_FEAT 2048
#define N_BINS 32
#define NSTRIPE 64
#define RPS (N_ROWS / NSTRIPE)   // 256 rows per stripe
#define TBL 65536
#define SMEM_BYTES (32768*4 + 2048*4*2)   // 147456: RPpack + isig + m2

// ---------------------------------------------------------------------------
// Scratch (static device globals; no allocation at runtime)
// ---------------------------------------------------------------------------
__device__ float              g_psum[NSTRIPE * N_FEAT];
__device__ float              g_psq [NSTRIPE * N_FEAT];
__device__ float              g_isig[N_FEAT];
__device__ float              g_m2  [N_FEAT];          // mean * isig
__device__ unsigned int       g_rppack[1024 * 32];     // bf16x2 RP, bank-swizzled
__device__ unsigned int       g_hash[N_ROWS];
__device__ unsigned int       g_slot[N_ROWS];
__device__ unsigned long long g_tkey[TBL];
__device__ unsigned int       g_tcnt[TBL];

// ---------------------------------------------------------------------------
// Helpers
// ---------------------------------------------------------------------------
__device__ __forceinline__ unsigned packbf(float lo, float hi) {
    unsigned d;
    asm("cvt.rn.bf16x2.f32 %0, %1, %2;" : "=r"(d) : "f"(hi), "f"(lo));
    return d;
}

__device__ __forceinline__ void mma16816(float* c,
                                         unsigned a0, unsigned a1, unsigned a2, unsigned a3,
                                         unsigned b0, unsigned b1) {
    asm volatile(
        "mma.sync.aligned.m16n8k16.row.col.f32.bf16.bf16.f32 "
        "{%0,%1,%2,%3}, {%4,%5,%6,%7}, {%8,%9}, {%0,%1,%2,%3};"
        : "+f"(c[0]), "+f"(c[1]), "+f"(c[2]), "+f"(c[3])
        : "r"(a0), "r"(a1), "r"(a2), "r"(a3), "r"(b0), "r"(b1));
}

__device__ __forceinline__ void table_insert(int i, unsigned h) {
    unsigned long long key = ((unsigned long long)h << 6) | (unsigned long long)(i & 63);
    unsigned long long m = key * 0x9E3779B97F4A7C15ULL;
    unsigned s = (unsigned)(m >> 48);   // 16-bit slot
    for (;;) {
        unsigned long long prev = atomicCAS(&g_tkey[s], ~0ULL, key);
        if (prev == ~0ULL || prev == key) {
            atomicAdd(&g_tcnt[s], 1u);
            g_slot[i] = s;
            return;
        }
        s = (s + 1) & (TBL - 1);
    }
}

// ---------------------------------------------------------------------------
// Kernel 1: per-stripe column partial sums (deterministic two-stage reduction)
// ---------------------------------------------------------------------------
__global__ void k_partial(const float* __restrict__ x) {
    int col = blockIdx.x * 256 + threadIdx.x;
    int r0  = blockIdx.y * RPS;
    const float* p = x + (size_t)r0 * N_FEAT + col;
    float s = 0.f, q = 0.f;
#pragma unroll 8
    for (int r = 0; r < RPS; r++) {
        float v = p[(size_t)r * N_FEAT];
        s += v;
        q = fmaf(v, v, q);
    }
    g_psum[blockIdx.y * N_FEAT + col] = s;
    g_psq [blockIdx.y * N_FEAT + col] = q;
}

// ---------------------------------------------------------------------------
// Kernel 2: finalize RunningMeanStd -> isig, mean*isig
// ---------------------------------------------------------------------------
__global__ void k_stats() {
    int col = blockIdx.x * 256 + threadIdx.x;
    float s = 0.f, q = 0.f;
    for (int st = 0; st < NSTRIPE; st++) {
        s += g_psum[st * N_FEAT + col];
        q += g_psq [st * N_FEAT + col];
    }
    const float n = 16384.0f;
    float bm = s / n;
    float bv = (q - bm * bm * n) / (n - 1.0f);       // unbiased variance
    const double nd = 16384.0, totd = 1e-4 + nd;
    float mean = bm * (float)(nd / totd);
    float m2v  = (1e-4f + bv * 16384.0f) + (bm * bm) * (float)(1e-4 * nd / totd);
    float var  = m2v / (float)totd;
    float sig  = sqrtf(var + 1e-8f);
    float isg  = 1.0f / sig;
    g_isig[col] = isg;
    g_m2[col]   = mean * isg;
}

// ---------------------------------------------------------------------------
// Kernel 3: pack RP to bf16x2, transposed to k-pair-major with bank swizzle
//   element (kk, col) stored at [kk*32 + (col ^ ((kk&3)<<3))]
// ---------------------------------------------------------------------------
__global__ void k_rpprep(const float* __restrict__ rp) {
    int idx = blockIdx.x * 256 + threadIdx.x;      // 0..32767
    int kk  = idx >> 5;                            // 0..1023 (k-pair index)
    int col = idx & 31;
    float lo = rp[(2 * kk)     * N_BINS + col];
    float hi = rp[(2 * kk + 1) * N_BINS + col];
    int scol = col ^ ((kk & 3) << 3);
    g_rppack[kk * 32 + scol] = packbf(lo, hi);
}

// ---------------------------------------------------------------------------
// Kernel 4: hash table init (must run every launch: graph replays)
// ---------------------------------------------------------------------------
__global__ void k_tinit() {
    int i = blockIdx.x * 256 + threadIdx.x;
    g_tkey[i] = ~0ULL;
    g_tcnt[i] = 0u;
}

// ---------------------------------------------------------------------------
// Kernel 5: fused normalize -> bf16 -> mma.sync projection -> sign hash ->
//           hash-table insert.  1 block = 128 rows (8 warps x 16 rows).
// ---------------------------------------------------------------------------
__global__ void __launch_bounds__(256, 1) k_project(const float* __restrict__ x) {
    extern __shared__ unsigned int smem[];          // [0,32768): RPpack
    float* sisig = (float*)(smem + 32768);          // [2048]
    float* sm2   = sisig + N_FEAT;                  // [2048]

    for (int idx = threadIdx.x; idx < 32768; idx += 256) smem[idx] = g_rppack[idx];
    for (int idx = threadIdx.x; idx < N_FEAT; idx += 256) {
        sisig[idx] = g_isig[idx];
        sm2[idx]   = g_m2[idx];
    }
    __syncthreads();

    int warp = threadIdx.x >> 5, lane = threadIdx.x & 31;
    int q = lane & 3, r = lane >> 2;
    int row0 = blockIdx.x * 128 + warp * 16;

    const float* xa = x + (size_t)(row0 + r) * N_FEAT + 2 * q;   // rows r / r+8
    const float* xb = xa + 8 * (size_t)N_FEAT;

    float acc[4][4];
#pragma unroll
    for (int t = 0; t < 4; t++)
#pragma unroll
        for (int c = 0; c < 4; c++) acc[t][c] = 0.f;

    unsigned scol[4];
#pragma unroll
    for (int t = 0; t < 4; t++) scol[t] = (unsigned)((t * 8 + r) ^ (q << 3));

#pragma unroll 2
    for (int k = 0; k < N_FEAT; k += 16) {
        float2 va = *(const float2*)(xa + k);
        float2 vb = *(const float2*)(xa + k + 8);
        float2 vc = *(const float2*)(xb + k);
        float2 vd = *(const float2*)(xb + k + 8);

        int c0 = k + 2 * q;
        float2 is0 = *(const float2*)(sisig + c0);
        float2 is1 = *(const float2*)(sisig + c0 + 8);
        float2 mm0 = *(const float2*)(sm2 + c0);
        float2 mm1 = *(const float2*)(sm2 + c0 + 8);

        // v = x*isig - mean*isig, packed to bf16x2 (lo = smaller k)
        unsigned a0 = packbf(fmaf(va.x, is0.x, -mm0.x), fmaf(va.y, is0.y, -mm0.y));
        unsigned a2 = packbf(fmaf(vb.x, is1.x, -mm1.x), fmaf(vb.y, is1.y, -mm1.y));
        unsigned a1 = packbf(fmaf(vc.x, is0.x, -mm0.x), fmaf(vc.y, is0.y, -mm0.y));
        unsigned a3 = packbf(fmaf(vd.x, is1.x, -mm1.x), fmaf(vd.y, is1.y, -mm1.y));

        int kk = (k >> 1) + q;
#pragma unroll
        for (int t = 0; t < 4; t++) {
            unsigned b0 = smem[kk * 32 + scol[t]];
            unsigned b1 = smem[(kk + 4) * 32 + scol[t]];
            mma16816(acc[t], a0, a1, a2, a3, b0, b1);
        }
    }

    // bits -> 32-bit hash per row.  acc[t][0/1]: row r, cols t*8+2q, +1
    //                               acc[t][2/3]: row r+8, same cols
    unsigned mlo = 0u, mhi = 0u;
#pragma unroll
    for (int t = 0; t < 4; t++) {
        int nb = t * 8 + 2 * q;
        mlo |= (acc[t][0] > 0.f ? 1u : 0u) << nb;
        mlo |= (acc[t][1] > 0.f ? 1u : 0u) << (nb + 1);
        mhi |= (acc[t][2] > 0.f ? 1u : 0u) << nb;
        mhi |= (acc[t][3] > 0.f ? 1u : 0u) << (nb + 1);
    }
    // OR across the 4 lanes of each row-quad
    mlo |= __shfl_xor_sync(0xffffffffu, mlo, 1);
    mlo |= __shfl_xor_sync(0xffffffffu, mlo, 2);
    mhi |= __shfl_xor_sync(0xffffffffu, mhi, 1);
    mhi |= __shfl_xor_sync(0xffffffffu, mhi, 2);

    if (q == 0) {
        int i0 = row0 + r, i1 = i0 + 8;
        g_hash[i0] = mlo;
        g_hash[i1] = mhi;
        table_insert(i0, mlo);
        table_insert(i1, mhi);
    }
}

// ---------------------------------------------------------------------------
// Kernel 6: rewards.  Unique keys (the overwhelming case) -> 1.0.
// Rare duplicates -> exact rank among earlier occurrences.
// ---------------------------------------------------------------------------
__global__ void k_final(float* __restrict__ out) {
    int i = blockIdx.x * 256 + threadIdx.x;
    unsigned s = g_slot[i];
    float v = 1.0f;
    if (g_tcnt[s] != 1u) {
        unsigned long long my = ((unsigned long long)g_hash[i] << 6) | (unsigned long long)(i & 63);
        int c = 1;
        for (int j = 0; j < i; j++) {
            unsigned long long kj = ((unsigned long long)g_hash[j] << 6) | (unsigned long long)(j & 63);
            c += (kj == my) ? 1 : 0;
        }
        v = 1.0f / sqrtf((float)c);
    }
    out[i] = v;
}

// ---------------------------------------------------------------------------
// Launch
// ---------------------------------------------------------------------------
extern "C" void kernel_launch(void* const* d_in, const int* in_sizes, int n_in,
                              void* d_out, int out_size) {
    const float* x  = (const float*)d_in[0];
    const float* rp = (const float*)d_in[1];
    if (in_sizes[0] == N_FEAT * N_BINS) {   // defensive: swap if metadata order differs
        const float* t = x; x = rp; rp = t;
    }
    float* out = (float*)d_out;

    // Idempotent opt-in for 144 KB dynamic smem (not a stream op; capture-safe)
    cudaFuncSetAttribute(k_project, cudaFuncAttributeMaxDynamicSharedMemorySize, SMEM_BYTES);

    k_rpprep <<<128, 256>>>(rp);
    k_tinit  <<<TBL / 256, 256>>>();
    k_partial<<<dim3(N_FEAT / 256, NSTRIPE), 256>>>(x);
    k_stats  <<<N_FEAT / 256, 256>>>();
    k_project<<<N_ROWS / 128, 256, SMEM_BYTES>>>(x);
    k_final  <<<N_ROWS / 256, 256>>>(out);
}

// round 2
// speedup vs baseline: 1.2062x; 1.2062x over previous
#include <cuda_runtime.h>
#include <cstdint>

// ---------------------------------------------------------------------------
// Problem constants
// ---------------------------------------------------------------------------
#define N_ROWS 16384      // 64 * 256
#define N_FEAT 2048
#define N_BINS 32
#define NSTRIPE 64
#define RPS (N_ROWS / NSTRIPE)     // 256 rows per stripe
#define TBL 65536
// split-K project: RP half (512 kk * 32 * 4B) + stats half (1024 * 2 * 4B)
#define PROJ_SMEM (512*32*4 + 1024*4*2)   // 73728

// ---------------------------------------------------------------------------
// Scratch (static device globals; no runtime allocation)
// ---------------------------------------------------------------------------
__device__ float              g_psum[NSTRIPE * N_FEAT];
__device__ float              g_psq [NSTRIPE * N_FEAT];
__device__ float              g_isig[N_FEAT];
__device__ float              g_m2  [N_FEAT];            // mean * isig
__device__ unsigned int       g_rppack[1024 * 32];       // bf16x2 RP, swizzled
__device__ float              g_part[2 * N_ROWS * N_BINS]; // split-K partials
__device__ unsigned int       g_hash[N_ROWS];
__device__ unsigned int       g_slot[N_ROWS];
__device__ unsigned long long g_tkey[TBL];
__device__ unsigned int       g_tcnt[TBL];

// ---------------------------------------------------------------------------
// Helpers
// ---------------------------------------------------------------------------
__device__ __forceinline__ unsigned packbf(float lo, float hi) {
    unsigned d;
    asm("cvt.rn.bf16x2.f32 %0, %1, %2;" : "=r"(d) : "f"(hi), "f"(lo));
    return d;
}

__device__ __forceinline__ void mma16816(float* c,
                                         unsigned a0, unsigned a1, unsigned a2, unsigned a3,
                                         unsigned b0, unsigned b1) {
    asm volatile(
        "mma.sync.aligned.m16n8k16.row.col.f32.bf16.bf16.f32 "
        "{%0,%1,%2,%3}, {%4,%5,%6,%7}, {%8,%9}, {%0,%1,%2,%3};"
        : "+f"(c[0]), "+f"(c[1]), "+f"(c[2]), "+f"(c[3])
        : "r"(a0), "r"(a1), "r"(a2), "r"(a3), "r"(b0), "r"(b1));
}

__device__ __forceinline__ void table_insert(int i, unsigned h) {
    unsigned long long key = ((unsigned long long)h << 6) | (unsigned long long)(i & 63);
    unsigned long long m = key * 0x9E3779B97F4A7C15ULL;
    unsigned s = (unsigned)(m >> 48);   // 16-bit slot
    for (;;) {
        unsigned long long prev = atomicCAS(&g_tkey[s], ~0ULL, key);
        if (prev == ~0ULL || prev == key) {
            atomicAdd(&g_tcnt[s], 1u);
            g_slot[i] = s;
            return;
        }
        s = (s + 1) & (TBL - 1);
    }
}

// ---------------------------------------------------------------------------
// Kernel 1 (fused): column partial sums + RP pack + hash-table init.
//   blocks [0,512)    : per-stripe column sums (the heavy part, launched first)
//   blocks [512,640)  : RP -> bf16x2 transposed pack with bank swizzle
//   blocks [640,896)  : table init
// ---------------------------------------------------------------------------
__global__ void k_pre(const float* __restrict__ x, const float* __restrict__ rp) {
    int b = blockIdx.x;
    if (b < 512) {
        int colblk = b & 7, stripe = b >> 3;
        int col = colblk * 256 + threadIdx.x;
        const float* p = x + (size_t)(stripe * RPS) * N_FEAT + col;
        float s = 0.f, q = 0.f;
#pragma unroll 8
        for (int r = 0; r < RPS; r++) {
            float v = p[(size_t)r * N_FEAT];
            s += v;
            q = fmaf(v, v, q);
        }
        g_psum[stripe * N_FEAT + col] = s;
        g_psq [stripe * N_FEAT + col] = q;
    } else if (b < 640) {
        int idx = (b - 512) * 256 + threadIdx.x;   // 0..32767
        int kk  = idx >> 5;                        // k-pair index 0..1023
        int col = idx & 31;
        float lo = rp[(2 * kk)     * N_BINS + col];
        float hi = rp[(2 * kk + 1) * N_BINS + col];
        int scol = col ^ ((kk & 3) << 3);
        g_rppack[kk * 32 + scol] = packbf(lo, hi);
    } else {
        int i = (b - 640) * 256 + threadIdx.x;
        g_tkey[i] = ~0ULL;
        g_tcnt[i] = 0u;
    }
}

// ---------------------------------------------------------------------------
// Kernel 2: finalize RunningMeanStd -> isig, mean*isig  (parallelized)
//   64 blocks x 256: 32 cols/block, 8 threads per column over stripes.
// ---------------------------------------------------------------------------
__global__ void k_stats() {
    __shared__ float ss[8][32], sq[8][32];
    int c = threadIdx.x & 31, g = threadIdx.x >> 5;
    int col = blockIdx.x * 32 + c;
    float s = 0.f, q = 0.f;
#pragma unroll
    for (int st = g; st < NSTRIPE; st += 8) {
        s += g_psum[st * N_FEAT + col];
        q += g_psq [st * N_FEAT + col];
    }
    ss[g][c] = s; sq[g][c] = q;
    __syncthreads();
    if (g == 0) {
#pragma unroll
        for (int j = 1; j < 8; j++) { s += ss[j][c]; q += sq[j][c]; }
        const float n = 16384.0f;
        float bm = s / n;
        float bv = (q - bm * bm * n) / (n - 1.0f);       // unbiased variance
        const double nd = 16384.0, totd = 1e-4 + nd;
        float mean = bm * (float)(nd / totd);
        float m2v  = (1e-4f + bv * 16384.0f) + (bm * bm) * (float)(1e-4 * nd / totd);
        float var  = m2v / (float)totd;
        float isg  = rsqrtf(var + 1e-8f) * rsqrtf(1.0f) ;  // keep precision path simple
        isg = 1.0f / sqrtf(var + 1e-8f);
        g_isig[col] = isg;
        g_m2[col]   = mean * isg;
    }
}

// ---------------------------------------------------------------------------
// Kernel 3: split-K fused normalize -> bf16 -> mma projection -> fp32 partials.
//   256 blocks: tile = bid>>1 (128 row-tiles of 128 rows), kh = bid&1 (k half).
//   72 KB smem -> 2 blocks/SM, all 256 blocks resident in one wave.
// ---------------------------------------------------------------------------
__global__ void __launch_bounds__(256, 2) k_project(const float* __restrict__ x) {
    extern __shared__ unsigned int smem[];          // [0,16384): RP half (64KB)
    float* sisig = (float*)(smem + 16384);          // [1024]
    float* sm2   = sisig + 1024;                    // [1024]

    int tile = blockIdx.x >> 1;
    int kh   = blockIdx.x & 1;
    int kbase = kh * 1024;                          // feature-column base

    // stage RP half (swizzle parity preserved: kh*512 is a multiple of 4)
    const unsigned* rpsrc = g_rppack + kh * 512 * 32;
    for (int idx = threadIdx.x; idx < 16384; idx += 256) smem[idx] = rpsrc[idx];
    for (int idx = threadIdx.x; idx < 1024; idx += 256) {
        sisig[idx] = g_isig[kbase + idx];
        sm2[idx]   = g_m2[kbase + idx];
    }
    __syncthreads();

    int warp = threadIdx.x >> 5, lane = threadIdx.x & 31;
    int q = lane & 3, r = lane >> 2;
    int row0 = tile * 128 + warp * 16;

    const float* xa = x + (size_t)(row0 + r) * N_FEAT + kbase + 2 * q;
    const float* xb = xa + 8 * (size_t)N_FEAT;

    float acc[4][4];
#pragma unroll
    for (int t = 0; t < 4; t++)
#pragma unroll
        for (int c = 0; c < 4; c++) acc[t][c] = 0.f;

    unsigned scol[4];
#pragma unroll
    for (int t = 0; t < 4; t++) scol[t] = (unsigned)((t * 8 + r) ^ (q << 3));

#pragma unroll 4
    for (int k = 0; k < 1024; k += 16) {
        float2 va = *(const float2*)(xa + k);
        float2 vb = *(const float2*)(xa + k + 8);
        float2 vc = *(const float2*)(xb + k);
        float2 vd = *(const float2*)(xb + k + 8);

        int c0 = k + 2 * q;
        float2 is0 = *(const float2*)(sisig + c0);
        float2 is1 = *(const float2*)(sisig + c0 + 8);
        float2 mm0 = *(const float2*)(sm2 + c0);
        float2 mm1 = *(const float2*)(sm2 + c0 + 8);

        unsigned a0 = packbf(fmaf(va.x, is0.x, -mm0.x), fmaf(va.y, is0.y, -mm0.y));
        unsigned a2 = packbf(fmaf(vb.x, is1.x, -mm1.x), fmaf(vb.y, is1.y, -mm1.y));
        unsigned a1 = packbf(fmaf(vc.x, is0.x, -mm0.x), fmaf(vc.y, is0.y, -mm0.y));
        unsigned a3 = packbf(fmaf(vd.x, is1.x, -mm1.x), fmaf(vd.y, is1.y, -mm1.y));

        int kk = (k >> 1) + q;
#pragma unroll
        for (int t = 0; t < 4; t++) {
            unsigned b0 = smem[kk * 32 + scol[t]];
            unsigned b1 = smem[(kk + 4) * 32 + scol[t]];
            mma16816(acc[t], a0, a1, a2, a3, b0, b1);
        }
    }

    // write fp32 partials: acc[t][0/1] -> row r, cols t*8+2q..+1 ; [2/3] -> row r+8
    float* dst = g_part + (size_t)kh * N_ROWS * N_BINS;
    int rowA = row0 + r, rowB = rowA + 8;
#pragma unroll
    for (int t = 0; t < 4; t++) {
        int cb = t * 8 + 2 * q;
        *(float2*)(dst + (size_t)rowA * N_BINS + cb) = make_float2(acc[t][0], acc[t][1]);
        *(float2*)(dst + (size_t)rowB * N_BINS + cb) = make_float2(acc[t][2], acc[t][3]);
    }
}

// ---------------------------------------------------------------------------
// Kernel 4: combine split-K partials -> sign hash -> table insert.
//   64 blocks x 256. Each warp pass covers 4 rows (8 lanes/row, float4 each).
// ---------------------------------------------------------------------------
__global__ void k_combine() {
    int warp = threadIdx.x >> 5, lane = threadIdx.x & 31;
    int lrow = lane >> 3, lcol = lane & 7;          // 4 rows x 8 col-groups
    int base = blockIdx.x * 256 + warp * 32;        // 32 rows per warp

    const float4* p0 = (const float4*)g_part;
    const float4* p1 = (const float4*)(g_part + (size_t)N_ROWS * N_BINS);

#pragma unroll
    for (int pass = 0; pass < 8; pass++) {
        int row = base + pass * 4 + lrow;
        float4 a = p0[row * 8 + lcol];
        float4 b = p1[row * 8 + lcol];
        int cb = lcol * 4;
        unsigned m = 0u;
        m |= ((a.x + b.x) > 0.f ? 1u : 0u) << (cb + 0);
        m |= ((a.y + b.y) > 0.f ? 1u : 0u) << (cb + 1);
        m |= ((a.z + b.z) > 0.f ? 1u : 0u) << (cb + 2);
        m |= ((a.w + b.w) > 0.f ? 1u : 0u) << (cb + 3);
        // OR across the 8 lanes of this row
        m |= __shfl_xor_sync(0xffffffffu, m, 1);
        m |= __shfl_xor_sync(0xffffffffu, m, 2);
        m |= __shfl_xor_sync(0xffffffffu, m, 4);
        if (lcol == 0) {
            g_hash[row] = m;
            table_insert(row, m);
        }
    }
}

// ---------------------------------------------------------------------------
// Kernel 5: rewards. Unique keys (overwhelming case) -> 1.0; rare duplicates
// get an exact sequential-occurrence rank.
// ---------------------------------------------------------------------------
__global__ void k_final(float* __restrict__ out) {
    int i = blockIdx.x * 256 + threadIdx.x;
    unsigned s = g_slot[i];
    float v = 1.0f;
    if (g_tcnt[s] != 1u) {
        unsigned long long my = ((unsigned long long)g_hash[i] << 6) | (unsigned long long)(i & 63);
        int c = 1;
        for (int j = 0; j < i; j++) {
            unsigned long long kj = ((unsigned long long)g_hash[j] << 6) | (unsigned long long)(j & 63);
            c += (kj == my) ? 1 : 0;
        }
        v = 1.0f / sqrtf((float)c);
    }
    out[i] = v;
}

// ---------------------------------------------------------------------------
// Launch
// ---------------------------------------------------------------------------
extern "C" void kernel_launch(void* const* d_in, const int* in_sizes, int n_in,
                              void* d_out, int out_size) {
    const float* x  = (const float*)d_in[0];
    const float* rp = (const float*)d_in[1];
    if (in_sizes[0] == N_FEAT * N_BINS) {   // defensive: swap if order differs
        const float* t = x; x = rp; rp = t;
    }
    float* out = (float*)d_out;

    cudaFuncSetAttribute(k_project, cudaFuncAttributeMaxDynamicSharedMemorySize, PROJ_SMEM);

    k_pre    <<<896, 256>>>(x, rp);
    k_stats  <<<64, 256>>>();
    k_project<<<256, 256, PROJ_SMEM>>>(x);
    k_combine<<<64, 256>>>();
    k_final  <<<64, 256>>>(out);
}

// round 3
// speedup vs baseline: 1.3600x; 1.1275x over previous
#include <cuda_runtime.h>
#include <cstdint>

// ---------------------------------------------------------------------------
// Problem constants
// ---------------------------------------------------------------------------
#define N_ROWS 16384      // 64 * 256
#define N_FEAT 2048
#define N_BINS 32
#define NSTRIPE 64
#define RPS (N_ROWS / NSTRIPE)     // 256 rows per stripe
#define TBL 65536
#define NTILE 128                  // 128-row tiles
// split-K project smem: RP half (512 kk * 32 * 4B) + stats half (1024 * 4B * 2)
#define PROJ_SMEM (512*32*4 + 1024*4*2)   // 73728

// ---------------------------------------------------------------------------
// Scratch (static device globals; no runtime allocation)
// ---------------------------------------------------------------------------
__device__ float              g_psum[NSTRIPE * N_FEAT];
__device__ float              g_psq [NSTRIPE * N_FEAT];
__device__ float              g_isig[N_FEAT];
__device__ float              g_m2  [N_FEAT];              // mean * isig
__device__ unsigned int       g_rppack[1024 * 32];         // bf16x2 RP, swizzled
__device__ float              g_part[2 * N_ROWS * N_BINS]; // split-K partials
__device__ unsigned int       g_tilecnt[NTILE];            // arrival counters
__device__ unsigned int       g_hash[N_ROWS];
__device__ unsigned int       g_slot[N_ROWS];
__device__ unsigned long long g_tkey[TBL];
__device__ unsigned int       g_tcnt[TBL];

// ---------------------------------------------------------------------------
// Helpers
// ---------------------------------------------------------------------------
__device__ __forceinline__ unsigned packbf(float lo, float hi) {
    unsigned d;
    asm("cvt.rn.bf16x2.f32 %0, %1, %2;" : "=r"(d) : "f"(hi), "f"(lo));
    return d;
}

__device__ __forceinline__ void mma16816(float* c,
                                         unsigned a0, unsigned a1, unsigned a2, unsigned a3,
                                         unsigned b0, unsigned b1) {
    asm volatile(
        "mma.sync.aligned.m16n8k16.row.col.f32.bf16.bf16.f32 "
        "{%0,%1,%2,%3}, {%4,%5,%6,%7}, {%8,%9}, {%0,%1,%2,%3};"
        : "+f"(c[0]), "+f"(c[1]), "+f"(c[2]), "+f"(c[3])
        : "r"(a0), "r"(a1), "r"(a2), "r"(a3), "r"(b0), "r"(b1));
}

__device__ __forceinline__ void table_insert(int i, unsigned h) {
    unsigned long long key = ((unsigned long long)h << 6) | (unsigned long long)(i & 63);
    unsigned long long m = key * 0x9E3779B97F4A7C15ULL;
    unsigned s = (unsigned)(m >> 48);   // 16-bit slot
    for (;;) {
        unsigned long long prev = atomicCAS(&g_tkey[s], ~0ULL, key);
        if (prev == ~0ULL || prev == key) {
            atomicAdd(&g_tcnt[s], 1u);
            g_slot[i] = s;
            return;
        }
        s = (s + 1) & (TBL - 1);
    }
}

// ---------------------------------------------------------------------------
// Kernel 1 (fused): column partial sums + RP pack + table/counter init.
// ---------------------------------------------------------------------------
__global__ void k_pre(const float* __restrict__ x, const float* __restrict__ rp) {
    int b = blockIdx.x;
    if (b < 512) {
        int colblk = b & 7, stripe = b >> 3;
        int col = colblk * 256 + threadIdx.x;
        const float* p = x + (size_t)(stripe * RPS) * N_FEAT + col;
        float s = 0.f, q = 0.f;
#pragma unroll 8
        for (int r = 0; r < RPS; r++) {
            float v = p[(size_t)r * N_FEAT];
            s += v;
            q = fmaf(v, v, q);
        }
        g_psum[stripe * N_FEAT + col] = s;
        g_psq [stripe * N_FEAT + col] = q;
    } else if (b < 640) {
        int idx = (b - 512) * 256 + threadIdx.x;   // 0..32767
        int kk  = idx >> 5;                        // k-pair index 0..1023
        int col = idx & 31;
        float lo = rp[(2 * kk)     * N_BINS + col];
        float hi = rp[(2 * kk + 1) * N_BINS + col];
        int scol = col ^ ((kk & 3) << 3);
        g_rppack[kk * 32 + scol] = packbf(lo, hi);
    } else {
        int i = (b - 640) * 256 + threadIdx.x;
        g_tkey[i] = ~0ULL;
        g_tcnt[i] = 0u;
        if (b == 640 && threadIdx.x < NTILE) g_tilecnt[threadIdx.x] = 0u;
    }
}

// ---------------------------------------------------------------------------
// Kernel 2: finalize RunningMeanStd -> isig, mean*isig
// ---------------------------------------------------------------------------
__global__ void k_stats() {
    __shared__ float ss[8][32], sq[8][32];
    int c = threadIdx.x & 31, g = threadIdx.x >> 5;
    int col = blockIdx.x * 32 + c;
    float s = 0.f, q = 0.f;
#pragma unroll
    for (int st = g; st < NSTRIPE; st += 8) {
        s += g_psum[st * N_FEAT + col];
        q += g_psq [st * N_FEAT + col];
    }
    ss[g][c] = s; sq[g][c] = q;
    __syncthreads();
    if (g == 0) {
#pragma unroll
        for (int j = 1; j < 8; j++) { s += ss[j][c]; q += sq[j][c]; }
        const float n = 16384.0f;
        float bm = s / n;
        float bv = (q - bm * bm * n) / (n - 1.0f);       // unbiased variance
        const double nd = 16384.0, totd = 1e-4 + nd;
        float mean = bm * (float)(nd / totd);
        float m2v  = (1e-4f + bv * 16384.0f) + (bm * bm) * (float)(1e-4 * nd / totd);
        float var  = m2v / (float)totd;
        float isg  = 1.0f / sqrtf(var + 1e-8f);
        g_isig[col] = isg;
        g_m2[col]   = mean * isg;
    }
}

// ---------------------------------------------------------------------------
// Kernel 3: split-K fused normalize -> bf16 -> mma projection -> fp32 partials
// -> (last-arriving half per tile) combine + sign hash + table insert.
//   256 blocks: tile = bid>>1, kh = bid&1. 72 KB smem -> 2 blocks/SM.
// ---------------------------------------------------------------------------
__global__ void __launch_bounds__(256, 2) k_project(const float* __restrict__ x) {
    extern __shared__ unsigned int smem[];          // [0,16384): RP half (64KB)
    float* sisig = (float*)(smem + 16384);          // [1024]
    float* sm2   = sisig + 1024;                    // [1024]
    __shared__ int s_last;

    int tile = blockIdx.x >> 1;
    int kh   = blockIdx.x & 1;
    int kbase = kh * 1024;

    const unsigned* rpsrc = g_rppack + kh * 512 * 32;   // swizzle parity kept
    for (int idx = threadIdx.x; idx < 16384; idx += 256) smem[idx] = rpsrc[idx];
    for (int idx = threadIdx.x; idx < 1024; idx += 256) {
        sisig[idx] = g_isig[kbase + idx];
        sm2[idx]   = g_m2[kbase + idx];
    }
    __syncthreads();

    int warp = threadIdx.x >> 5, lane = threadIdx.x & 31;
    int q = lane & 3, r = lane >> 2;
    int row0 = tile * 128 + warp * 16;

    const float* xa = x + (size_t)(row0 + r) * N_FEAT + kbase + 2 * q;
    const float* xb = xa + 8 * (size_t)N_FEAT;

    float acc[4][4];
#pragma unroll
    for (int t = 0; t < 4; t++)
#pragma unroll
        for (int c = 0; c < 4; c++) acc[t][c] = 0.f;

    unsigned scol[4];
#pragma unroll
    for (int t = 0; t < 4; t++) scol[t] = (unsigned)((t * 8 + r) ^ (q << 3));

#pragma unroll 4
    for (int k = 0; k < 1024; k += 16) {
        float2 va = *(const float2*)(xa + k);
        float2 vb = *(const float2*)(xa + k + 8);
        float2 vc = *(const float2*)(xb + k);
        float2 vd = *(const float2*)(xb + k + 8);

        int c0 = k + 2 * q;
        float2 is0 = *(const float2*)(sisig + c0);
        float2 is1 = *(const float2*)(sisig + c0 + 8);
        float2 mm0 = *(const float2*)(sm2 + c0);
        float2 mm1 = *(const float2*)(sm2 + c0 + 8);

        unsigned a0 = packbf(fmaf(va.x, is0.x, -mm0.x), fmaf(va.y, is0.y, -mm0.y));
        unsigned a2 = packbf(fmaf(vb.x, is1.x, -mm1.x), fmaf(vb.y, is1.y, -mm1.y));
        unsigned a1 = packbf(fmaf(vc.x, is0.x, -mm0.x), fmaf(vc.y, is0.y, -mm0.y));
        unsigned a3 = packbf(fmaf(vd.x, is1.x, -mm1.x), fmaf(vd.y, is1.y, -mm1.y));

        int kk = (k >> 1) + q;
#pragma unroll
        for (int t = 0; t < 4; t++) {
            unsigned b0 = smem[kk * 32 + scol[t]];
            unsigned b1 = smem[(kk + 4) * 32 + scol[t]];
            mma16816(acc[t], a0, a1, a2, a3, b0, b1);
        }
    }

    // publish my half's partials
    float* dst = g_part + (size_t)kh * N_ROWS * N_BINS;
    int rowA = row0 + r, rowB = rowA + 8;
#pragma unroll
    for (int t = 0; t < 4; t++) {
        int cb = t * 8 + 2 * q;
        *(float2*)(dst + (size_t)rowA * N_BINS + cb) = make_float2(acc[t][0], acc[t][1]);
        *(float2*)(dst + (size_t)rowB * N_BINS + cb) = make_float2(acc[t][2], acc[t][3]);
    }
    __threadfence();
    if (threadIdx.x == 0) s_last = (int)atomicAdd(&g_tilecnt[tile], 1u);
    __syncthreads();
    if (s_last != 1) return;       // first-arriving half is done
    __threadfence();               // make peer's partials visible

    // last-arriving half: add peer partials (L2-resident) to register accs
    const float* src = g_part + (size_t)(1 - kh) * N_ROWS * N_BINS;
    unsigned mlo = 0u, mhi = 0u;
#pragma unroll
    for (int t = 0; t < 4; t++) {
        int cb = t * 8 + 2 * q;
        float2 pa = *(const float2*)(src + (size_t)rowA * N_BINS + cb);
        float2 pb = *(const float2*)(src + (size_t)rowB * N_BINS + cb);
        mlo |= ((acc[t][0] + pa.x) > 0.f ? 1u : 0u) << cb;
        mlo |= ((acc[t][1] + pa.y) > 0.f ? 1u : 0u) << (cb + 1);
        mhi |= ((acc[t][2] + pb.x) > 0.f ? 1u : 0u) << cb;
        mhi |= ((acc[t][3] + pb.y) > 0.f ? 1u : 0u) << (cb + 1);
    }
    mlo |= __shfl_xor_sync(0xffffffffu, mlo, 1);
    mlo |= __shfl_xor_sync(0xffffffffu, mlo, 2);
    mhi |= __shfl_xor_sync(0xffffffffu, mhi, 1);
    mhi |= __shfl_xor_sync(0xffffffffu, mhi, 2);

    if (q == 0) {
        g_hash[rowA] = mlo;
        g_hash[rowB] = mhi;
        table_insert(rowA, mlo);
        table_insert(rowB, mhi);
    }
}

// ---------------------------------------------------------------------------
// Kernel 4: rewards. Unique keys -> 1.0; rare duplicates get exact rank.
// ---------------------------------------------------------------------------
__global__ void k_final(float* __restrict__ out) {
    int i = blockIdx.x * 256 + threadIdx.x;
    unsigned s = g_slot[i];
    float v = 1.0f;
    if (g_tcnt[s] != 1u) {
        unsigned long long my = ((unsigned long long)g_hash[i] << 6) | (unsigned long long)(i & 63);
        int c = 1;
        for (int j = 0; j < i; j++) {
            unsigned long long kj = ((unsigned long long)g_hash[j] << 6) | (unsigned long long)(j & 63);
            c += (kj == my) ? 1 : 0;
        }
        v = 1.0f / sqrtf((float)c);
    }
    out[i] = v;
}

// ---------------------------------------------------------------------------
// Launch
// ---------------------------------------------------------------------------
extern "C" void kernel_launch(void* const* d_in, const int* in_sizes, int n_in,
                              void* d_out, int out_size) {
    const float* x  = (const float*)d_in[0];
    const float* rp = (const float*)d_in[1];
    if (in_sizes[0] == N_FEAT * N_BINS) {   // defensive: swap if order differs
        const float* t = x; x = rp; rp = t;
    }
    float* out = (float*)d_out;

    cudaFuncSetAttribute(k_project, cudaFuncAttributeMaxDynamicSharedMemorySize, PROJ_SMEM);

    k_pre    <<<896, 256>>>(x, rp);
    k_stats  <<<64, 256>>>();
    k_project<<<256, 256, PROJ_SMEM>>>(x);
    k_final  <<<64, 256>>>(out);
}